// round 4
// baseline (speedup 1.0000x reference)
#include <cuda_runtime.h>
#include <cuda_fp16.h>
#include <mma.h>
#include <math.h>

using namespace nvcuda;

// Problem constants
constexpr int B_  = 4;
constexpr int S_  = 2048;
constexpr int E_  = 1152;
constexpr int H_  = 12;
constexpr int D_  = 96;
constexpr int HD_ = H_ * D_;     // 1152
constexpr int M_  = B_ * S_;     // 8192
constexpr int BH_ = B_ * H_;     // 48

// ---------------------------------------------------------------------------
// Scratch (device globals: the allocation-free path)
// ---------------------------------------------------------------------------
__device__ __half g_logits_h[(size_t)M_ * E_];
__device__ __half g_Wq_h[(size_t)E_ * HD_];
__device__ __half g_Wk_h[(size_t)E_ * HD_];
__device__ __half g_Wv_h[(size_t)E_ * HD_];
__device__ __half g_Wo_h[(size_t)HD_ * E_];
__device__ float  g_qf[(size_t)M_ * HD_];
__device__ float  g_kf[(size_t)M_ * HD_];
__device__ float  g_vf[(size_t)M_ * HD_];
__device__ __half g_qh[(size_t)M_ * HD_];
__device__ __half g_kh[(size_t)M_ * HD_];
__device__ __half g_vh[(size_t)M_ * HD_];
__device__ float  g_scores[(size_t)BH_ * S_ * S_];   // 805 MB
__device__ __half g_P[(size_t)BH_ * S_ * S_];        // 402 MB
__device__ float  g_ctxf[(size_t)M_ * HD_];
__device__ __half g_ctxh[(size_t)M_ * HD_];

// ---------------------------------------------------------------------------
// Elementwise converts
// ---------------------------------------------------------------------------
__global__ void cvt_inputs(const float* __restrict__ logits,
                           const float* __restrict__ Wq,
                           const float* __restrict__ Wk,
                           const float* __restrict__ Wv,
                           const float* __restrict__ Wo) {
    int i = blockIdx.x * blockDim.x + threadIdx.x;
    if (i < M_ * E_) g_logits_h[i] = __float2half(logits[i]);
    if (i < E_ * HD_) {
        g_Wq_h[i] = __float2half(Wq[i]);
        g_Wk_h[i] = __float2half(Wk[i]);
        g_Wv_h[i] = __float2half(Wv[i]);
        g_Wo_h[i] = __float2half(Wo[i]);
    }
}

__global__ void cvt_ctx() {
    int i = blockIdx.x * blockDim.x + threadIdx.x;
    if (i < M_ * HD_) g_ctxh[i] = __float2half(g_ctxf[i]);
}

__global__ void add_bias_out(float* __restrict__ out, const float* __restrict__ bo) {
    int i = blockIdx.x * blockDim.x + threadIdx.x;
    if (i < M_ * E_) out[i] += bo[i % E_];
}

// ---------------------------------------------------------------------------
// Generic 8192x1152x1152 GEMM body (C = A[M,1152] @ B[1152,1152], fp16 in,
// fp32 out). Block tile 64x64, BK=16, 8 warps, each warp a 16x32 C tile.
// grid = (1152/64, 8192/64), block = 256.
// ---------------------------------------------------------------------------
__device__ __forceinline__ void gemm1152(const __half* __restrict__ A,
                                         const __half* __restrict__ Bw,
                                         float* __restrict__ C) {
    __shared__ __half As[64][24];   // ld 24 (48B, 16B-multiple)
    __shared__ __half Bs[16][72];   // ld 72 (144B, 16B-multiple)
    const int bm = blockIdx.y * 64;
    const int bn = blockIdx.x * 64;
    const int tid = threadIdx.x;
    const int warp = tid >> 5;
    const int wr = warp >> 1, wc = warp & 1;

    wmma::fragment<wmma::accumulator, 16, 16, 16, float> acc[2];
    wmma::fill_fragment(acc[0], 0.0f);
    wmma::fill_fragment(acc[1], 0.0f);

    for (int k0 = 0; k0 < 1152; k0 += 16) {
        if (tid < 128) {
            int r = tid >> 1, q = tid & 1;
            *reinterpret_cast<uint4*>(&As[r][q * 8]) =
                *reinterpret_cast<const uint4*>(&A[(size_t)(bm + r) * 1152 + k0 + q * 8]);
        } else {
            int t = tid - 128;
            int r = t >> 3, q = t & 7;
            *reinterpret_cast<uint4*>(&Bs[r][q * 8]) =
                *reinterpret_cast<const uint4*>(&Bw[(size_t)(k0 + r) * 1152 + bn + q * 8]);
        }
        __syncthreads();
        wmma::fragment<wmma::matrix_a, 16, 16, 16, __half, wmma::row_major> af;
        wmma::load_matrix_sync(af, &As[wr * 16][0], 24);
#pragma unroll
        for (int j = 0; j < 2; ++j) {
            wmma::fragment<wmma::matrix_b, 16, 16, 16, __half, wmma::row_major> bf;
            wmma::load_matrix_sync(bf, &Bs[0][wc * 32 + j * 16], 72);
            wmma::mma_sync(acc[j], af, bf, acc[j]);
        }
        __syncthreads();
    }
#pragma unroll
    for (int j = 0; j < 2; ++j)
        wmma::store_matrix_sync(&C[(size_t)(bm + wr * 16) * 1152 + bn + wc * 32 + j * 16],
                                acc[j], 1152, wmma::mem_row_major);
}

__global__ __launch_bounds__(256) void gemm_q()  { gemm1152(g_logits_h, g_Wq_h, g_qf); }
__global__ __launch_bounds__(256) void gemm_k()  { gemm1152(g_logits_h, g_Wk_h, g_kf); }
__global__ __launch_bounds__(256) void gemm_v()  { gemm1152(g_logits_h, g_Wv_h, g_vf); }
__global__ __launch_bounds__(256) void gemm_o(float* __restrict__ C) {
    gemm1152(g_ctxh, g_Wo_h, C);
}

// ---------------------------------------------------------------------------
// RoPE + bias + fp16 pack for q,k; bias + fp16 pack for v.
// One thread per (b,s,h,pair). Angles computed to match the fp32 reference:
// theta in double (rounds to the reference's fp32 theta), angle = fp32 s*theta,
// sin/cos in double (safe under --use_fast_math at angles ~2000 rad).
// ---------------------------------------------------------------------------
__global__ void rope_pack(const float* __restrict__ bq,
                          const float* __restrict__ bk,
                          const float* __restrict__ bv) {
    const int NP = B_ * S_ * H_ * (D_ / 2);
    int gid = blockIdx.x * blockDim.x + threadIdx.x;
    if (gid >= NP) return;
    int j = gid % (D_ / 2);
    int t = gid / (D_ / 2);
    int h = t % H_; t /= H_;
    int s = t % S_;
    int b = t / S_;

    const size_t base = ((size_t)(b * S_ + s) * H_ + h) * D_ + 2 * j;
    const int bidx = h * D_ + 2 * j;

    double theta = exp(-(2.0 * (double)j / (double)D_) * log(10000.0));
    float angf = (float)s * (float)theta;
    double sn, cs;
    sincos((double)angf, &sn, &cs);
    float c = (float)cs, snf = (float)sn;

    float q0 = g_qf[base]     + bq[bidx];
    float q1 = g_qf[base + 1] + bq[bidx + 1];
    g_qh[base]     = __float2half(q0 * c - q1 * snf);
    g_qh[base + 1] = __float2half(q1 * c + q0 * snf);

    float k0 = g_kf[base]     + bk[bidx];
    float k1 = g_kf[base + 1] + bk[bidx + 1];
    g_kh[base]     = __float2half(k0 * c - k1 * snf);
    g_kh[base + 1] = __float2half(k1 * c + k0 * snf);

    g_vh[base]     = __float2half(g_vf[base]     + bv[bidx]);
    g_vh[base + 1] = __float2half(g_vf[base + 1] + bv[bidx + 1]);
}

// ---------------------------------------------------------------------------
// scores[bh, q, k] = Q_bh[q,:] . K_bh[k,:]   (unscaled; causal blocks skipped)
// grid = (S/64 keys, S/64 queries, BH), block = 256.
// ---------------------------------------------------------------------------
__global__ __launch_bounds__(256) void attn_scores() {
    const int kb = blockIdx.x * 64;
    const int qb = blockIdx.y * 64;
    if (kb > qb) return;                       // entire 64x64 tile masked
    const int bh = blockIdx.z, b = bh / H_, h = bh % H_;
    const __half* Q = g_qh + (size_t)b * S_ * HD_ + h * D_;
    const __half* K = g_kh + (size_t)b * S_ * HD_ + h * D_;
    float* Sc = g_scores + (size_t)bh * S_ * S_;

    __shared__ __half Qs[64][104];   // 96 + 8 pad, ld 104 (208B, 16B-multiple)
    __shared__ __half Ks[64][104];
    const int tid = threadIdx.x;

    for (int i = tid; i < 768; i += 256) {     // 64 rows x 12 uint4
        int r = i / 12, q = i % 12;
        *reinterpret_cast<uint4*>(&Qs[r][q * 8]) =
            *reinterpret_cast<const uint4*>(&Q[(size_t)(qb + r) * HD_ + q * 8]);
        *reinterpret_cast<uint4*>(&Ks[r][q * 8]) =
            *reinterpret_cast<const uint4*>(&K[(size_t)(kb + r) * HD_ + q * 8]);
    }
    __syncthreads();

    const int warp = tid >> 5, wr = warp >> 1, wc = warp & 1;
    wmma::fragment<wmma::accumulator, 16, 16, 16, float> acc[2];
    wmma::fill_fragment(acc[0], 0.0f);
    wmma::fill_fragment(acc[1], 0.0f);
#pragma unroll
    for (int kk = 0; kk < 96; kk += 16) {
        wmma::fragment<wmma::matrix_a, 16, 16, 16, __half, wmma::row_major> af;
        wmma::load_matrix_sync(af, &Qs[wr * 16][kk], 104);
#pragma unroll
        for (int j = 0; j < 2; ++j) {
            // B = K^T: col_major over the row-major K tile
            wmma::fragment<wmma::matrix_b, 16, 16, 16, __half, wmma::col_major> bf;
            wmma::load_matrix_sync(bf, &Ks[wc * 32 + j * 16][kk], 104);
            wmma::mma_sync(acc[j], af, bf, acc[j]);
        }
    }
#pragma unroll
    for (int j = 0; j < 2; ++j)
        wmma::store_matrix_sync(&Sc[(size_t)(qb + wr * 16) * S_ + kb + wc * 32 + j * 16],
                                acc[j], S_, wmma::mem_row_major);
}

// ---------------------------------------------------------------------------
// Causal row softmax: P[bh,q,k] = softmax(scale * scores[bh,q,0..q]); 0 beyond.
// One block (256 threads) per row; row cached in smem (<= 8 KB).
// ---------------------------------------------------------------------------
__global__ __launch_bounds__(256) void softmax_causal() {
    const int row = blockIdx.x;
    const int bh = row >> 11;           // / S_
    const int q  = row & (S_ - 1);
    const float* src = g_scores + (size_t)bh * S_ * S_ + (size_t)q * S_;
    __half* dst      = g_P      + (size_t)bh * S_ * S_ + (size_t)q * S_;
    const int n = q + 1;
    const int tid = threadIdx.x;
    const float scale = 0.10206207261596577f;   // 1/sqrt(96)

    __shared__ float buf[S_];
    __shared__ float red[8];

    float m = -1e30f;
    for (int i = tid; i < n; i += 256) {
        float v = src[i] * scale;
        buf[i] = v;
        m = fmaxf(m, v);
    }
#pragma unroll
    for (int o = 16; o; o >>= 1) m = fmaxf(m, __shfl_xor_sync(0xffffffffu, m, o));
    if ((tid & 31) == 0) red[tid >> 5] = m;
    __syncthreads();
    float mAll = red[0];
#pragma unroll
    for (int w = 1; w < 8; ++w) mAll = fmaxf(mAll, red[w]);
    __syncthreads();

    float ssum = 0.0f;
    for (int i = tid; i < n; i += 256) {
        float e = expf(buf[i] - mAll);
        buf[i] = e;
        ssum += e;
    }
#pragma unroll
    for (int o = 16; o; o >>= 1) ssum += __shfl_xor_sync(0xffffffffu, ssum, o);
    if ((tid & 31) == 0) red[tid >> 5] = ssum;
    __syncthreads();
    float tot = 0.0f;
#pragma unroll
    for (int w = 0; w < 8; ++w) tot += red[w];
    const float inv = 1.0f / tot;

    for (int i = tid; i < S_; i += 256) {
        float v = (i < n) ? buf[i] * inv : 0.0f;
        dst[i] = __float2half(v);
    }
}

// ---------------------------------------------------------------------------
// ctx[bh, q, :] = P[bh, q, :] @ V_bh       (K-loop causally bounded)
// grid = (1, S/64, BH), block = 256. Block tile 64 x 96.
// ---------------------------------------------------------------------------
__global__ __launch_bounds__(256) void attn_ctx() {
    const int qb = blockIdx.y * 64;
    const int bh = blockIdx.z, b = bh / H_, h = bh % H_;
    const __half* P = g_P + (size_t)bh * S_ * S_;
    const __half* V = g_vh + (size_t)b * S_ * HD_ + h * D_;
    float* C = g_ctxf + (size_t)b * S_ * HD_ + h * D_;

    __shared__ __half Ps[64][24];
    __shared__ __half Vs[16][104];
    const int tid = threadIdx.x;
    const int warp = tid >> 5, wr = warp >> 1, wc = warp & 1;

    wmma::fragment<wmma::accumulator, 16, 16, 16, float> acc[3];
#pragma unroll
    for (int j = 0; j < 3; ++j) wmma::fill_fragment(acc[j], 0.0f);

    const int kmax = qb + 64;                  // causal bound (P is 0 beyond q)
    for (int k0 = 0; k0 < kmax; k0 += 16) {
        if (tid < 128) {
            int r = tid >> 1, q = tid & 1;
            *reinterpret_cast<uint4*>(&Ps[r][q * 8]) =
                *reinterpret_cast<const uint4*>(&P[(size_t)(qb + r) * S_ + k0 + q * 8]);
        } else {
            int t = tid - 128;
            for (int i = t; i < 192; i += 128) {   // 16 rows x 12 uint4
                int r = i / 12, q = i % 12;
                *reinterpret_cast<uint4*>(&Vs[r][q * 8]) =
                    *reinterpret_cast<const uint4*>(&V[(size_t)(k0 + r) * HD_ + q * 8]);
            }
        }
        __syncthreads();
        wmma::fragment<wmma::matrix_a, 16, 16, 16, __half, wmma::row_major> af;
        wmma::load_matrix_sync(af, &Ps[wr * 16][0], 24);
#pragma unroll
        for (int j = 0; j < 3; ++j) {
            wmma::fragment<wmma::matrix_b, 16, 16, 16, __half, wmma::row_major> bf;
            wmma::load_matrix_sync(bf, &Vs[0][wc * 48 + j * 16], 104);
            wmma::mma_sync(acc[j], af, bf, acc[j]);
        }
        __syncthreads();
    }
#pragma unroll
    for (int j = 0; j < 3; ++j)
        wmma::store_matrix_sync(&C[(size_t)(qb + wr * 16) * HD_ + wc * 48 + j * 16],
                                acc[j], HD_, wmma::mem_row_major);
}

// ---------------------------------------------------------------------------
// Launch
// ---------------------------------------------------------------------------
extern "C" void kernel_launch(void* const* d_in, const int* in_sizes, int n_in,
                              void* d_out, int out_size) {
    (void)in_sizes; (void)n_in; (void)out_size;
    const float* logits = (const float*)d_in[0];
    const float* Wq = (const float*)d_in[1];
    const float* bq = (const float*)d_in[2];
    const float* Wk = (const float*)d_in[3];
    const float* bk = (const float*)d_in[4];
    const float* Wv = (const float*)d_in[5];
    const float* bv = (const float*)d_in[6];
    const float* Wo = (const float*)d_in[7];
    const float* bo = (const float*)d_in[8];
    float* out = (float*)d_out;

    cvt_inputs<<<(M_ * E_ + 255) / 256, 256>>>(logits, Wq, Wk, Wv, Wo);

    dim3 gproj(HD_ / 64, M_ / 64);            // (18, 128)
    gemm_q<<<gproj, 256>>>();
    gemm_k<<<gproj, 256>>>();
    gemm_v<<<gproj, 256>>>();

    rope_pack<<<(B_ * S_ * H_ * (D_ / 2) + 255) / 256, 256>>>(bq, bk, bv);

    attn_scores<<<dim3(S_ / 64, S_ / 64, BH_), 256>>>();
    softmax_causal<<<BH_ * S_, 256>>>();
    attn_ctx<<<dim3(1, S_ / 64, BH_), 256>>>();

    cvt_ctx<<<(M_ * HD_ + 255) / 256, 256>>>();
    gemm_o<<<dim3(E_ / 64, M_ / 64), 256>>>(out);
    add_bias_out<<<(M_ * E_ + 255) / 256, 256>>>(out, bo);
}

// round 5
// speedup vs baseline: 1.3209x; 1.3209x over previous
#include <cuda_runtime.h>
#include <cuda_fp16.h>
#include <mma.h>
#include <math.h>

using namespace nvcuda;

// Problem constants
constexpr int B_  = 4;
constexpr int S_  = 2048;
constexpr int E_  = 1152;
constexpr int H_  = 12;
constexpr int D_  = 96;
constexpr int HD_ = H_ * D_;     // 1152
constexpr int QKV_ = 3 * HD_;    // 3456
constexpr int M_  = B_ * S_;     // 8192
constexpr int BH_ = B_ * H_;     // 48

// ---------------------------------------------------------------------------
// Scratch (device globals: the allocation-free path)
// ---------------------------------------------------------------------------
__device__ __half g_logits_h[(size_t)M_ * E_];
__device__ __half g_Wqkv_h[(size_t)E_ * QKV_];
__device__ __half g_Wo_h[(size_t)HD_ * E_];
__device__ float  g_qkvf[(size_t)M_ * QKV_];
__device__ __half g_qh[(size_t)M_ * HD_];
__device__ __half g_kh[(size_t)M_ * HD_];
__device__ __half g_vh[(size_t)M_ * HD_];
__device__ float  g_scores[(size_t)BH_ * S_ * S_];   // 805 MB
__device__ __half g_P[(size_t)BH_ * S_ * S_];        // 402 MB
__device__ __half g_ctxh[(size_t)M_ * HD_];

// ---------------------------------------------------------------------------
// cp.async helpers
// ---------------------------------------------------------------------------
__device__ __forceinline__ unsigned smem_u32(const void* p) {
    return (unsigned)__cvta_generic_to_shared(p);
}
__device__ __forceinline__ void cp16(unsigned s, const void* g) {
    asm volatile("cp.async.cg.shared.global [%0], [%1], 16;\n" :: "r"(s), "l"(g));
}
__device__ __forceinline__ void cp_commit() {
    asm volatile("cp.async.commit_group;\n");
}
__device__ __forceinline__ void cp_wait0() {
    asm volatile("cp.async.wait_group 0;\n");
}

// ---------------------------------------------------------------------------
// Elementwise converts
// ---------------------------------------------------------------------------
__global__ void cvt_inputs(const float* __restrict__ logits,
                           const float* __restrict__ Wq,
                           const float* __restrict__ Wk,
                           const float* __restrict__ Wv,
                           const float* __restrict__ Wo) {
    int i = blockIdx.x * blockDim.x + threadIdx.x;
    if (i < M_ * E_) g_logits_h[i] = __float2half(logits[i]);
    if (i < E_ * HD_) {
        int r = i / HD_, c = i % HD_;
        size_t o = (size_t)r * QKV_ + c;
        g_Wqkv_h[o]           = __float2half(Wq[i]);
        g_Wqkv_h[o + HD_]     = __float2half(Wk[i]);
        g_Wqkv_h[o + 2 * HD_] = __float2half(Wv[i]);
        g_Wo_h[i] = __float2half(Wo[i]);
    }
}

__global__ void add_bias_out(float* __restrict__ out, const float* __restrict__ bo) {
    int i = blockIdx.x * blockDim.x + threadIdx.x;
    if (i < M_ * E_) out[i] += bo[i % E_];
}

// ---------------------------------------------------------------------------
// Big GEMM: C[M,N] = A[M,1152] @ B[1152,N], fp16 in, fp32 out.
// Block tile 128x128, BK=32, double-buffered cp.async, 8 warps (4x2),
// each warp a 32x64 C tile (2x4 accum fragments).
// grid = (N/128, M/128), block = 256.
// ---------------------------------------------------------------------------
template<int N>
__global__ __launch_bounds__(256, 2) void gemm_big(const __half* __restrict__ A,
                                                   const __half* __restrict__ Bw,
                                                   float* __restrict__ C) {
    __shared__ __half As[2][128][40];    // ld 40 (80B)
    __shared__ __half Bs[2][32][136];    // ld 136 (272B)
    const int bm = blockIdx.y * 128;
    const int bn = blockIdx.x * 128;
    const int tid = threadIdx.x;
    const int warp = tid >> 5, wr = warp >> 1, wc = warp & 1;

    // A: 128 rows x 4 uint4/row = 512 uint4; thread covers rows ar0, ar0+64
    const int ar0 = tid >> 2, ac = (tid & 3) * 8;
    // B: 32 rows x 16 uint4/row = 512 uint4; thread covers rows br0, br0+16
    const int br0 = tid >> 4, bc = (tid & 15) * 8;

    wmma::fragment<wmma::accumulator, 16, 16, 16, float> acc[2][4];
#pragma unroll
    for (int i = 0; i < 2; ++i)
#pragma unroll
        for (int j = 0; j < 4; ++j) wmma::fill_fragment(acc[i][j], 0.0f);

    // prologue: issue tile 0
    {
        cp16(smem_u32(&As[0][ar0][ac]),      &A[(size_t)(bm + ar0) * 1152 + ac]);
        cp16(smem_u32(&As[0][ar0 + 64][ac]), &A[(size_t)(bm + ar0 + 64) * 1152 + ac]);
        cp16(smem_u32(&Bs[0][br0][bc]),      &Bw[(size_t)br0 * N + bn + bc]);
        cp16(smem_u32(&Bs[0][br0 + 16][bc]), &Bw[(size_t)(br0 + 16) * N + bn + bc]);
        cp_commit();
    }

    int buf = 0;
    constexpr int NIT = 1152 / 32;       // 36
    for (int it = 0; it < NIT; ++it) {
        cp_wait0();
        __syncthreads();
        if (it + 1 < NIT) {
            const int k0 = (it + 1) * 32;
            const int nb = buf ^ 1;
            cp16(smem_u32(&As[nb][ar0][ac]),      &A[(size_t)(bm + ar0) * 1152 + k0 + ac]);
            cp16(smem_u32(&As[nb][ar0 + 64][ac]), &A[(size_t)(bm + ar0 + 64) * 1152 + k0 + ac]);
            cp16(smem_u32(&Bs[nb][br0][bc]),      &Bw[(size_t)(k0 + br0) * N + bn + bc]);
            cp16(smem_u32(&Bs[nb][br0 + 16][bc]), &Bw[(size_t)(k0 + br0 + 16) * N + bn + bc]);
            cp_commit();
        }
#pragma unroll
        for (int kk = 0; kk < 32; kk += 16) {
            wmma::fragment<wmma::matrix_a, 16, 16, 16, __half, wmma::row_major> a0, a1;
            wmma::load_matrix_sync(a0, &As[buf][wr * 32][kk], 40);
            wmma::load_matrix_sync(a1, &As[buf][wr * 32 + 16][kk], 40);
#pragma unroll
            for (int j = 0; j < 4; ++j) {
                wmma::fragment<wmma::matrix_b, 16, 16, 16, __half, wmma::row_major> bf;
                wmma::load_matrix_sync(bf, &Bs[buf][kk][wc * 64 + j * 16], 136);
                wmma::mma_sync(acc[0][j], a0, bf, acc[0][j]);
                wmma::mma_sync(acc[1][j], a1, bf, acc[1][j]);
            }
        }
        buf ^= 1;
    }

#pragma unroll
    for (int i = 0; i < 2; ++i)
#pragma unroll
        for (int j = 0; j < 4; ++j)
            wmma::store_matrix_sync(
                &C[(size_t)(bm + wr * 32 + i * 16) * N + bn + wc * 64 + j * 16],
                acc[i][j], N, wmma::mem_row_major);
}

// ---------------------------------------------------------------------------
// RoPE + bias + fp16 pack for q,k; bias + fp16 pack for v. Reads fused qkv.
// ---------------------------------------------------------------------------
__global__ void rope_pack(const float* __restrict__ bq,
                          const float* __restrict__ bk,
                          const float* __restrict__ bv) {
    const int NP = B_ * S_ * H_ * (D_ / 2);
    int gid = blockIdx.x * blockDim.x + threadIdx.x;
    if (gid >= NP) return;
    int j = gid % (D_ / 2);
    int t = gid / (D_ / 2);
    int h = t % H_; t /= H_;
    int s = t % S_;
    int b = t / S_;

    const size_t row = (size_t)(b * S_ + s);
    const int col = h * D_ + 2 * j;
    const size_t src = row * QKV_ + col;
    const size_t dst = row * HD_ + col;

    double theta = exp(-(2.0 * (double)j / (double)D_) * log(10000.0));
    float angf = (float)s * (float)theta;
    double sn, cs;
    sincos((double)angf, &sn, &cs);
    float c = (float)cs, snf = (float)sn;

    float q0 = g_qkvf[src]     + bq[col];
    float q1 = g_qkvf[src + 1] + bq[col + 1];
    g_qh[dst]     = __float2half(q0 * c - q1 * snf);
    g_qh[dst + 1] = __float2half(q1 * c + q0 * snf);

    float k0 = g_qkvf[src + HD_]     + bk[col];
    float k1 = g_qkvf[src + HD_ + 1] + bk[col + 1];
    g_kh[dst]     = __float2half(k0 * c - k1 * snf);
    g_kh[dst + 1] = __float2half(k1 * c + k0 * snf);

    g_vh[dst]     = __float2half(g_qkvf[src + 2 * HD_]     + bv[col]);
    g_vh[dst + 1] = __float2half(g_qkvf[src + 2 * HD_ + 1] + bv[col + 1]);
}

// ---------------------------------------------------------------------------
// scores[bh,q,k] = scale * Q.K  on a 128(q) x 64(k) tile; K=96 resident.
// 8 warps 4x2, each 32x32 (2x2 accums). grid = (S/64, S/128, BH).
// ---------------------------------------------------------------------------
__global__ __launch_bounds__(256) void attn_scores() {
    const int kb = blockIdx.x * 64;
    const int qb = blockIdx.y * 128;
    if (kb >= qb + 128) return;                 // fully masked
    const int bh = blockIdx.z, b = bh / H_, h = bh % H_;
    const __half* Q = g_qh + (size_t)b * S_ * HD_ + h * D_;
    const __half* K = g_kh + (size_t)b * S_ * HD_ + h * D_;
    float* Sc = g_scores + (size_t)bh * S_ * S_;

    __shared__ __half Qs[128][104];
    __shared__ __half Ks[64][104];
    const int tid = threadIdx.x;

    for (int i = tid; i < 1536; i += 256) {     // 128 rows x 12 uint4
        int r = i / 12, q = i % 12;
        *reinterpret_cast<uint4*>(&Qs[r][q * 8]) =
            *reinterpret_cast<const uint4*>(&Q[(size_t)(qb + r) * HD_ + q * 8]);
    }
    for (int i = tid; i < 768; i += 256) {      // 64 rows x 12 uint4
        int r = i / 12, q = i % 12;
        *reinterpret_cast<uint4*>(&Ks[r][q * 8]) =
            *reinterpret_cast<const uint4*>(&K[(size_t)(kb + r) * HD_ + q * 8]);
    }
    __syncthreads();

    const int warp = tid >> 5, wr = warp >> 1, wc = warp & 1;
    wmma::fragment<wmma::accumulator, 16, 16, 16, float> acc[2][2];
#pragma unroll
    for (int i = 0; i < 2; ++i)
#pragma unroll
        for (int j = 0; j < 2; ++j) wmma::fill_fragment(acc[i][j], 0.0f);

#pragma unroll
    for (int kk = 0; kk < 96; kk += 16) {
        wmma::fragment<wmma::matrix_a, 16, 16, 16, __half, wmma::row_major> a0, a1;
        wmma::load_matrix_sync(a0, &Qs[wr * 32][kk], 104);
        wmma::load_matrix_sync(a1, &Qs[wr * 32 + 16][kk], 104);
#pragma unroll
        for (int j = 0; j < 2; ++j) {
            wmma::fragment<wmma::matrix_b, 16, 16, 16, __half, wmma::col_major> bf;
            wmma::load_matrix_sync(bf, &Ks[wc * 32 + j * 16][kk], 104);
            wmma::mma_sync(acc[0][j], a0, bf, acc[0][j]);
            wmma::mma_sync(acc[1][j], a1, bf, acc[1][j]);
        }
    }
    const float scale = 0.10206207261596577f;   // 1/sqrt(96)
#pragma unroll
    for (int i = 0; i < 2; ++i)
#pragma unroll
        for (int j = 0; j < 2; ++j) {
#pragma unroll
            for (int e = 0; e < acc[i][j].num_elements; ++e) acc[i][j].x[e] *= scale;
            wmma::store_matrix_sync(
                &Sc[(size_t)(qb + wr * 32 + i * 16) * S_ + kb + wc * 32 + j * 16],
                acc[i][j], S_, wmma::mem_row_major);
        }
}

// ---------------------------------------------------------------------------
// Causal row softmax (scores already scaled). One block per row.
// ---------------------------------------------------------------------------
__global__ __launch_bounds__(256) void softmax_causal() {
    const int row = blockIdx.x;
    const int bh = row >> 11;
    const int q  = row & (S_ - 1);
    const float* src = g_scores + (size_t)bh * S_ * S_ + (size_t)q * S_;
    __half* dst      = g_P      + (size_t)bh * S_ * S_ + (size_t)q * S_;
    const int n = q + 1;
    const int tid = threadIdx.x;

    __shared__ float buf[S_];
    __shared__ float red[8];

    float m = -1e30f;
    for (int i = tid; i < n; i += 256) {
        float v = src[i];
        buf[i] = v;
        m = fmaxf(m, v);
    }
#pragma unroll
    for (int o = 16; o; o >>= 1) m = fmaxf(m, __shfl_xor_sync(0xffffffffu, m, o));
    if ((tid & 31) == 0) red[tid >> 5] = m;
    __syncthreads();
    float mAll = red[0];
#pragma unroll
    for (int w = 1; w < 8; ++w) mAll = fmaxf(mAll, red[w]);
    __syncthreads();

    float ssum = 0.0f;
    for (int i = tid; i < n; i += 256) {
        float e = expf(buf[i] - mAll);
        buf[i] = e;
        ssum += e;
    }
#pragma unroll
    for (int o = 16; o; o >>= 1) ssum += __shfl_xor_sync(0xffffffffu, ssum, o);
    if ((tid & 31) == 0) red[tid >> 5] = ssum;
    __syncthreads();
    float tot = 0.0f;
#pragma unroll
    for (int w = 0; w < 8; ++w) tot += red[w];
    const float inv = 1.0f / tot;

    for (int i = tid; i < S_; i += 256) {
        float v = (i < n) ? buf[i] * inv : 0.0f;
        dst[i] = __float2half(v);
    }
}

// ---------------------------------------------------------------------------
// ctx[bh,q,:] = P[bh,q,:] @ V_bh.  128(q) x 96(d) tile, BK=64, causal bound.
// 8 warps 4x2, each 32x48 (2x3 accums). Epilogue writes fp16 via smem stage.
// grid = (1, S/128, BH).
// ---------------------------------------------------------------------------
__global__ __launch_bounds__(256) void attn_ctx() {
    const int qb = blockIdx.y * 128;
    const int bh = blockIdx.z, b = bh / H_, h = bh % H_;
    const __half* P = g_P + (size_t)bh * S_ * S_;
    const __half* V = g_vh + (size_t)b * S_ * HD_ + h * D_;

    __shared__ __half Ps[128][72];
    __shared__ __half Vs[64][104];
    __shared__ float stage[8][16][24];
    const int tid = threadIdx.x;
    const int warp = tid >> 5, wr = warp >> 1, wc = warp & 1;
    const int lane = tid & 31;

    wmma::fragment<wmma::accumulator, 16, 16, 16, float> acc[2][3];
#pragma unroll
    for (int i = 0; i < 2; ++i)
#pragma unroll
        for (int j = 0; j < 3; ++j) wmma::fill_fragment(acc[i][j], 0.0f);

    const int kmax = qb + 128;                 // causal bound (P zero beyond)
    for (int k0 = 0; k0 < kmax; k0 += 64) {
#pragma unroll
        for (int u = 0; u < 4; ++u) {          // Ps: 128 rows x 8 uint4 = 1024
            int idx = tid + 256 * u;
            int r = idx >> 3, c = (idx & 7) * 8;
            *reinterpret_cast<uint4*>(&Ps[r][c]) =
                *reinterpret_cast<const uint4*>(&P[(size_t)(qb + r) * S_ + k0 + c]);
        }
#pragma unroll
        for (int u = 0; u < 3; ++u) {          // Vs: 64 rows x 12 uint4 = 768
            int idx = tid + 256 * u;
            int r = idx / 12, c = (idx % 12) * 8;
            *reinterpret_cast<uint4*>(&Vs[r][c]) =
                *reinterpret_cast<const uint4*>(&V[(size_t)(k0 + r) * HD_ + c]);
        }
        __syncthreads();
#pragma unroll
        for (int kk = 0; kk < 64; kk += 16) {
            wmma::fragment<wmma::matrix_a, 16, 16, 16, __half, wmma::row_major> a0, a1;
            wmma::load_matrix_sync(a0, &Ps[wr * 32][kk], 72);
            wmma::load_matrix_sync(a1, &Ps[wr * 32 + 16][kk], 72);
#pragma unroll
            for (int j = 0; j < 3; ++j) {
                wmma::fragment<wmma::matrix_b, 16, 16, 16, __half, wmma::row_major> bf;
                wmma::load_matrix_sync(bf, &Vs[kk][wc * 48 + j * 16], 104);
                wmma::mma_sync(acc[0][j], a0, bf, acc[0][j]);
                wmma::mma_sync(acc[1][j], a1, bf, acc[1][j]);
            }
        }
        __syncthreads();
    }

    // Epilogue: per-fragment stage to smem fp32, convert to fp16 global.
#pragma unroll
    for (int i = 0; i < 2; ++i)
#pragma unroll
        for (int j = 0; j < 3; ++j) {
            wmma::store_matrix_sync(&stage[warp][0][0], acc[i][j], 24,
                                    wmma::mem_row_major);
            __syncwarp();
#pragma unroll
            for (int t = 0; t < 8; ++t) {
                int idx = lane * 8 + t;
                int r = idx >> 4, c = idx & 15;
                size_t o = (size_t)(b * S_ + qb + wr * 32 + i * 16 + r) * HD_ +
                           h * D_ + wc * 48 + j * 16 + c;
                g_ctxh[o] = __float2half(stage[warp][r][c]);
            }
            __syncwarp();
        }
}

// ---------------------------------------------------------------------------
// Launch
// ---------------------------------------------------------------------------
extern "C" void kernel_launch(void* const* d_in, const int* in_sizes, int n_in,
                              void* d_out, int out_size) {
    (void)in_sizes; (void)n_in; (void)out_size;
    const float* logits = (const float*)d_in[0];
    const float* Wq = (const float*)d_in[1];
    const float* bq = (const float*)d_in[2];
    const float* Wk = (const float*)d_in[3];
    const float* bk = (const float*)d_in[4];
    const float* Wv = (const float*)d_in[5];
    const float* bv = (const float*)d_in[6];
    const float* Wo = (const float*)d_in[7];
    const float* bo = (const float*)d_in[8];
    float* out = (float*)d_out;

    cvt_inputs<<<(M_ * E_ + 255) / 256, 256>>>(logits, Wq, Wk, Wv, Wo);

    {   // fused QKV projection: [8192,1152] @ [1152,3456]
        __half* A; cudaGetSymbolAddress((void**)&A, g_logits_h);
        __half* W; cudaGetSymbolAddress((void**)&W, g_Wqkv_h);
        float*  C; cudaGetSymbolAddress((void**)&C, g_qkvf);
        gemm_big<QKV_><<<dim3(QKV_ / 128, M_ / 128), 256>>>(A, W, C);
    }

    rope_pack<<<(B_ * S_ * H_ * (D_ / 2) + 255) / 256, 256>>>(bq, bk, bv);

    attn_scores<<<dim3(S_ / 64, S_ / 128, BH_), 256>>>();
    softmax_causal<<<BH_ * S_, 256>>>();
    attn_ctx<<<dim3(1, S_ / 128, BH_), 256>>>();

    {   // output projection: [8192,1152] @ [1152,1152] -> out
        __half* A; cudaGetSymbolAddress((void**)&A, g_ctxh);
        __half* W; cudaGetSymbolAddress((void**)&W, g_Wo_h);
        gemm_big<E_><<<dim3(E_ / 128, M_ / 128), 256>>>(A, W, out);
    }
    add_bias_out<<<(M_ * E_ + 255) / 256, 256>>>(out, bo);
}